// round 16
// baseline (speedup 1.0000x reference)
#include <cuda_runtime.h>
#include <cuda_fp16.h>
#include <cstdint>
#include <math_constants.h>

// MiniRocket via mma.sync (HMMA) fp16 GEMM, round 16.
// R16 = R15 + (a) packed __hmax2 running max (epilogue 10->8 ops per block),
// (b) branch-free 78-iteration main loop (tail chunk 156 handled separately
// for tz=1 only), (c) dead-code cleanup. Warp tile 32j x 32t, K=112 fp16,
// 7 ksteps, 2-stage ring, 6 CTAs/SM, grid 2560 (t-split 2), atomic combine.

#define LSEQ    5000
#define PADX    2112
#define ROWLEN  9224            // PADX + LSEQ + PADX
#define NCH     12
#define NROWS   192             // 16 batch * 12 ch
#define NFULL   78              // full chunks per t-half
#define ASTRIDE 240             // A row stride bytes (112 fp16 + pad), 16 | 240
#define OUTN    (16 * 20000)

#define BSZ     7168            // 56 rows x 128B per stage
#define A1OFF   (2 * BSZ)       // 14336: persistent A (mt=1, 64 rows x 240B)
#define SMEMSZ  (A1OFF + 64 * ASTRIDE)   // 29696 -> 6 CTAs/SM

typedef unsigned u32;

// fp16 x, 8 shifted padded copies: g_xh[s*NROWS + row][p] = x[row][p + s - PADX]
__device__ __align__(16) __half g_xh[8 * NROWS * ROWLEN];

// ---------------- prep: padded fp16, 8 shifts ----------------
__global__ void prep_kernel(const float* __restrict__ x) {
    int p2 = blockIdx.x * 256 + threadIdx.x;
    if (p2 >= ROWLEN / 2) return;
    int row = blockIdx.y;                      // 0..191
    int s   = blockIdx.z;                      // 0..7
    int p   = p2 * 2;

    float v0 = 0.f, v1 = 0.f;
    int i0 = p + s - PADX, i1 = i0 + 1;
    if (i0 >= 0 && i0 < LSEQ) v0 = x[(size_t)row * LSEQ + i0];
    if (i1 >= 0 && i1 < LSEQ) v1 = x[(size_t)row * LSEQ + i1];

    __half2 h;
    h.x = __float2half(v0);
    h.y = __float2half(v1);
    *reinterpret_cast<__half2*>(g_xh + ((size_t)s * NROWS + row) * ROWLEN + p) = h;
}

// ---------------- out init / finalize (atomic combine support) ----------------
__device__ __forceinline__ u32 fkey(float f) {
    u32 u = __float_as_uint(f);
    return (u & 0x80000000u) ? ~u : (u | 0x80000000u);
}
__global__ void init_kernel(float* out) {
    int i = blockIdx.x * 256 + threadIdx.x;
    if (i < OUTN) reinterpret_cast<u32*>(out)[i] = 0u;   // 0 < key(any finite)
}
__global__ void fin_kernel(float* out) {
    int i = blockIdx.x * 256 + threadIdx.x;
    if (i >= OUTN) return;
    int sub = (i % 20000) % 2000;
    if (sub < 1000) {
        u32 k = reinterpret_cast<u32*>(out)[i];
        out[i] = (k & 0x80000000u) ? __uint_as_float(k & 0x7FFFFFFFu)
                                   : __uint_as_float(~k);
    } else {
        out[i] = out[i] * (1.0f / (float)LSEQ);
    }
}

// ---------------- PTX helpers (baseline, sm_80+) ----------------
__device__ __forceinline__ u32 smem_u32(const void* p) {
    u32 a;
    asm("{ .reg .u64 t; cvta.to.shared.u64 t, %1; cvt.u32.u64 %0, t; }"
        : "=r"(a) : "l"(p));
    return a;
}
__device__ __forceinline__ void ldsm_x4(u32& r0, u32& r1, u32& r2, u32& r3, u32 a) {
    asm volatile("ldmatrix.sync.aligned.m8n8.x4.shared.b16 {%0,%1,%2,%3}, [%4];"
                 : "=r"(r0), "=r"(r1), "=r"(r2), "=r"(r3) : "r"(a));
}
__device__ __forceinline__ void ldsm_x4t(u32& r0, u32& r1, u32& r2, u32& r3, u32 a) {
    asm volatile("ldmatrix.sync.aligned.m8n8.x4.trans.shared.b16 {%0,%1,%2,%3}, [%4];"
                 : "=r"(r0), "=r"(r1), "=r"(r2), "=r"(r3) : "r"(a));
}
__device__ __forceinline__ void mma16816(float* d, const u32* a, u32 b0, u32 b1) {
    asm volatile(
        "mma.sync.aligned.m16n8k16.row.col.f32.f16.f16.f32 "
        "{%0,%1,%2,%3}, {%4,%5,%6,%7}, {%8,%9}, {%0,%1,%2,%3};"
        : "+f"(d[0]), "+f"(d[1]), "+f"(d[2]), "+f"(d[3])
        : "r"(a[0]), "r"(a[1]), "r"(a[2]), "r"(a[3]), "r"(b0), "r"(b1));
}
__device__ __forceinline__ void cp16(u32 dst, const void* src) {
    asm volatile("cp.async.cg.shared.global [%0], [%1], 16;"
                 :: "r"(dst), "l"(src) : "memory");
}
#define CP_COMMIT() asm volatile("cp.async.commit_group;" ::: "memory")
#define CP_WAIT(n)  asm volatile("cp.async.wait_group %0;" :: "n"(n) : "memory")

// ---------------- main kernel ----------------
__global__ void __launch_bounds__(128, 6)
mr_hmma(const float* __restrict__ W, const float* __restrict__ bias,
        float* __restrict__ out)
{
    extern __shared__ __align__(1024) char smem[];
    const u32 sb = smem_u32(smem);
    const int tid  = threadIdx.x;
    const int wid  = tid >> 5;      // 0..3
    const int lane = tid & 31;

    const int jt = blockIdx.x;              // 0..7
    const int b  = blockIdx.y;              // 0..15
    const int di = blockIdx.z >> 1;         // 0..9
    const int tz = blockIdx.z & 1;          // 0..1 (t half)
    const int d  = 1 << di;

    const int ci0 = tz ? NFULL : 0;         // first chunk index

    // ---- phase 1: stage A mt=0 rows (j&16==0) at slot*ASTRIDE (scratch) ----
    for (int e = tid; e < 64 * 56; e += 128) {
        int slot = e / 56;
        int kk   = (e - slot * 56) * 2;
        int j    = (slot >> 4) * 32 + (slot & 15);
        u32 val = 0;
        int jg = jt * 128 + j;
        if (jg < 1000 && kk < 108) {
            float2 w2 = *reinterpret_cast<const float2*>(
                W + (size_t)(di * 1000 + jg) * 108 + kk);
            __half2 h;
            h.x = __float2half(w2.x);
            h.y = __float2half(w2.y);
            val = *reinterpret_cast<u32*>(&h);
        }
        *reinterpret_cast<u32*>(smem + slot * ASTRIDE + kk * 2) = val;
    }
    __syncthreads();

    // ---- A mt=0 fragments -> registers (7 ksteps x 4 regs = 28) ----
    u32 afr[7][4];
    {
        u32 abase = sb + (u32)(wid * 16 + (lane & 15)) * ASTRIDE
                  + (u32)(lane >> 4) * 16;
#pragma unroll
        for (int q = 0; q < 7; q++)
            ldsm_x4(afr[q][0], afr[q][1], afr[q][2], afr[q][3], abase + q * 32);
    }
    __syncthreads();   // scratch free

    // ---- phase 2: stage A mt=1 rows (j&16) into persistent A1 ----
    for (int e = tid; e < 64 * 56; e += 128) {
        int slot = e / 56;
        int kk   = (e - slot * 56) * 2;
        int j    = (slot >> 4) * 32 + (slot & 15) + 16;
        u32 val = 0;
        int jg = jt * 128 + j;
        if (jg < 1000 && kk < 108) {
            float2 w2 = *reinterpret_cast<const float2*>(
                W + (size_t)(di * 1000 + jg) * 108 + kk);
            __half2 h;
            h.x = __float2half(w2.x);
            h.y = __float2half(w2.y);
            val = *reinterpret_cast<u32*>(&h);
        }
        *reinterpret_cast<u32*>(smem + A1OFF + slot * ASTRIDE + kk * 2) = val;
    }
    const u32 a1base = sb + (u32)A1OFF
                     + (u32)(wid * 16 + (lane & 15)) * ASTRIDE
                     + (u32)(lane >> 4) * 16;

    // ---- staging descriptors: 4 slots/thread (432 valid of 512) ----
    u32 so[4];  // element offset into g_xh, biased by ci0 (advance 32/chunk)
    u32 sd[4];  // swizzled smem byte offset (~0 = invalid)
#pragma unroll
    for (int sx = 0; sx < 4; sx++) {
        int e = tid + (sx << 7);
        bool valid = e < 108 * 4;
        int s  = valid ? (e >> 2) : 0;
        int ch = e & 3;
        int c = s / 9, k = s - c * 9;
        int o0 = PADX + (k - 4) * d + ch * 8;
        int s8 = o0 & 7, p0 = o0 - s8;
        so[sx] = (u32)((s8 * NROWS + b * NCH + c) * ROWLEN + p0)
               + (u32)ci0 * 32u;
        int u = s >> 1, half = s & 1;
        u32 off = (u32)u * 128u + ((u32)((half * 4 + ch) ^ (u & 7)) * 16u);
        sd[sx] = valid ? off : 0xFFFFFFFFu;
    }

    // ---- zero pad slots 108..111 in both stages ----
    if (tid < 32) {
        int st = tid >> 4, idx = tid & 15;
        int s = 108 + (idx >> 2), ch = idx & 3;
        int u = s >> 1, half = s & 1;
        u32 off = (u32)u * 128u + ((u32)((half * 4 + ch) ^ (u & 7)) * 16u);
        *reinterpret_cast<uint4*>(smem + st * BSZ + off) = make_uint4(0, 0, 0, 0);
    }
    __syncthreads();   // A1 + pads written before loop reads/writes stages

    // ---- prologue: async-stage first chunk ----
    const __half* gx = g_xh;
#pragma unroll
    for (int sx = 0; sx < 4; sx++)
        if (sd[sx] != 0xFFFFFFFFu) cp16(sb + sd[sx], gx + so[sx]);
    CP_COMMIT();

    // ---- per-lane ldsm-B address components ----
    const u32 laneU    = (u32)((lane & 15) >> 1);
    const u32 laneHalf = (u32)(lane & 1);
    const u32 g0       = (u32)(lane >> 4);
    const u32 laneBase = laneU * 128u;
    u32 xvo[2];
#pragma unroll
    for (int p = 0; p < 2; p++)
        xvo[p] = ((laneHalf * 4u + g0 + 2u * (u32)p) ^ laneU) * 16u;

    // ---- epilogue state: lane owns 4 j rows; max + counts packed half2 ----
    const int qd  = lane >> 2;
    const int j0w = jt * 128 + wid * 32;
    __half2 bvh[4], cnt2[4], mx2[4];
#pragma unroll
    for (int r = 0; r < 4; r++) {
        int j = j0w + qd + ((r & 1) << 3) + ((r >> 1) << 4);
        float bvv = (j < 1000) ? bias[di * 1000 + j] : 0.0f;
        bvh[r]  = __float2half2_rn(bvv);
        cnt2[r] = __float2half2_rn(0.0f);
        mx2[r]  = __float2half2_rn(-65504.0f);
    }

    // one 16-t half: MMA p-half from stage base bb, epilogue over ntmax n-tiles
    auto phalf = [&](u32 bb, int p, int ntmax) {
        float dacc[2][2][4];
#pragma unroll
        for (int mt = 0; mt < 2; mt++)
#pragma unroll
            for (int n = 0; n < 2; n++)
#pragma unroll
                for (int r = 0; r < 4; r++) dacc[mt][n][r] = 0.f;

#pragma unroll
        for (int q = 0; q < 7; q++) {
            u32 b0, b1, b2, b3;
            ldsm_x4t(b0, b1, b2, b3, bb + (u32)q * 1024u + xvo[p]);
            u32 a1[4];
            ldsm_x4(a1[0], a1[1], a1[2], a1[3], a1base + (u32)q * 32u);
            mma16816(dacc[0][0], afr[q], b0, b1);
            mma16816(dacc[0][1], afr[q], b2, b3);
            mma16816(dacc[1][0], a1, b0, b1);
            mma16816(dacc[1][1], a1, b2, b3);
        }
#pragma unroll
        for (int n = 0; n < 2; n++) {
            if (n < ntmax) {
#pragma unroll
                for (int mt = 0; mt < 2; mt++) {
                    __half2 pk0 = __floats2half2_rn(dacc[mt][n][0], dacc[mt][n][1]);
                    __half2 pk1 = __floats2half2_rn(dacc[mt][n][2], dacc[mt][n][3]);
                    mx2[2 * mt]      = __hmax2(mx2[2 * mt],      pk0);
                    mx2[2 * mt + 1]  = __hmax2(mx2[2 * mt + 1],  pk1);
                    cnt2[2 * mt]     = __hadd2(cnt2[2 * mt],
                                               __hgt2(pk0, bvh[2 * mt]));
                    cnt2[2 * mt + 1] = __hadd2(cnt2[2 * mt + 1],
                                               __hgt2(pk1, bvh[2 * mt + 1]));
                }
            }
        }
    };

    // ---- main loop: 78 full chunks, branch-light ----
    u32 cs   = 0;        // byte offset of stage holding current chunk
    u32 eoff = 32;       // element offset (rel. to so[]) of next chunk
    const int pfmax = NFULL - 1 + tz;   // prefetch while r < pfmax

    for (int r = 0; r < NFULL; r++) {
        CP_WAIT(0);            // current chunk resident
        __syncthreads();       // visible; other stage fully drained

        if (r < pfmax) {
            const u32 bw = sb + (cs ^ (u32)BSZ);
#pragma unroll
            for (int sx = 0; sx < 4; sx++)
                if (sd[sx] != 0xFFFFFFFFu)
                    cp16(bw + sd[sx], gx + so[sx] + eoff);
        }
        CP_COMMIT();
        eoff += 32;

        const u32 bb = sb + cs + laneBase;
        phalf(bb, 0, 2);
        phalf(bb, 1, 2);
        cs ^= (u32)BSZ;
    }

    // ---- tail (tz==1 only): chunk 156, t 4992..4999 -> p=0, n=0 ----
    if (tz) {
        CP_WAIT(0);
        __syncthreads();
        phalf(sb + cs + laneBase, 0, 1);
    }

    // ---- reduce across the 4 lanes of each quad; atomic combine ----
    float m[4], cf[4];
#pragma unroll
    for (int r = 0; r < 4; r++) {
        m[r]  = fmaxf(__low2float(mx2[r]), __high2float(mx2[r]));
        cf[r] = __low2float(cnt2[r]) + __high2float(cnt2[r]);
    }
#pragma unroll
    for (int o = 1; o < 4; o <<= 1) {
#pragma unroll
        for (int r = 0; r < 4; r++) {
            m[r]  = fmaxf(m[r], __shfl_xor_sync(0xffffffffu, m[r], o));
            cf[r] += __shfl_xor_sync(0xffffffffu, cf[r], o);
        }
    }
    if ((lane & 3) == 0) {
        float* ob = out + (size_t)b * 20000 + di * 2000;
#pragma unroll
        for (int r = 0; r < 4; r++) {
            int j = j0w + qd + ((r & 1) << 3) + ((r >> 1) << 4);
            if (j < 1000) {
                atomicMax(reinterpret_cast<u32*>(ob + j), fkey(m[r]));
                atomicAdd(ob + 1000 + j, cf[r]);
            }
        }
    }
}

extern "C" void kernel_launch(void* const* d_in, const int* in_sizes, int n_in,
                              void* d_out, int out_size)
{
    const float* x    = (const float*)d_in[0];  // [16,12,5000]
    const float* W    = (const float*)d_in[1];  // [10,1000,12,9]
    const float* bias = (const float*)d_in[2];  // [10,1000]
    float* out = (float*)d_out;                 // [16,20000]

    dim3 pg((ROWLEN / 2 + 255) / 256, NROWS, 8);
    prep_kernel<<<pg, 256>>>(x);

    init_kernel<<<(OUTN + 255) / 256, 256>>>(out);

    cudaFuncSetAttribute(mr_hmma, cudaFuncAttributeMaxDynamicSharedMemorySize, SMEMSZ);
    dim3 grid(8, 16, 20);                       // z = di*2 + tz
    mr_hmma<<<grid, 128, SMEMSZ>>>(W, bias, out);

    fin_kernel<<<(OUTN + 255) / 256, 256>>>(out);
}